// round 1
// baseline (speedup 1.0000x reference)
#include <cuda_runtime.h>
#include <cuda_bf16.h>
#include <math.h>

#define B     16
#define CIN   512
#define COUT  512
#define SD    512
#define H     32
#define W     32
#define KK    9

#define CONV_SCALE 0.014731391274719736f   // 1/sqrt(512*9)
#define MOD_SCALE  0.044194173824159216f   // 1/sqrt(512)
#define SQRT2      1.4142135623730951f

#define TC     16   // couts per block
#define CCHUNK 8    // cin per smem chunk

// ---------------- scratch (no allocations allowed) ----------------
__device__ float g_s    [B * CIN];
__device__ float g_s2   [B * CIN];
__device__ float g_demod[B * COUT];
__device__ float g_wsq  [COUT * CIN];            // conv_scale^2 * sum_kk w^2, [cout][cin]
__device__ float g_wt   [CIN * KK * COUT];       // conv_scale * w, [cin][kk][cout]

// ---------------- kernel 1: style modulation s = style @ (mod_w^T * scale) + mod_b
__global__ void k_style(const float* __restrict__ style,
                        const float* __restrict__ mod_w,
                        const float* __restrict__ mod_b) {
    int b = blockIdx.x;
    __shared__ float st[SD];
    for (int i = threadIdx.x; i < SD; i += 256) st[i] = style[b * SD + i];
    __syncthreads();
    int warp = threadIdx.x >> 5, lane = threadIdx.x & 31;
    for (int cin = warp; cin < CIN; cin += 8) {
        const float* mw = mod_w + cin * SD;
        float sum = 0.f;
        for (int d = lane; d < SD; d += 32) sum += mw[d] * st[d];
        #pragma unroll
        for (int o = 16; o; o >>= 1) sum += __shfl_xor_sync(0xFFFFFFFFu, sum, o);
        if (lane == 0) {
            float s = sum * MOD_SCALE + mod_b[cin];
            g_s [b * CIN + cin] = s;
            g_s2[b * CIN + cin] = s * s;
        }
    }
}

// ---------------- kernel 2: weight transpose (+scale) and per-(cout,cin) sum of squares
__global__ void k_prep_weight(const float* __restrict__ weight) {
    int cin  = blockIdx.x;      // 512 blocks
    int cout = threadIdx.x;     // 512 threads
    const float* wp = weight + (cout * CIN + cin) * KK;
    float ss = 0.f;
    #pragma unroll
    for (int kk = 0; kk < KK; kk++) {
        float w = wp[kk];
        ss += w * w;
        g_wt[(cin * KK + kk) * COUT + cout] = w * CONV_SCALE;
    }
    g_wsq[cout * CIN + cin] = ss * (CONV_SCALE * CONV_SCALE);
}

// ---------------- kernel 3: demod[b][cout] = rsqrt(sum_cin wsq*s^2 + 1e-8)
__global__ void k_demod() {
    int b = blockIdx.y;
    int cout0 = blockIdx.x * 64;
    __shared__ float s2s[CIN];
    for (int i = threadIdx.x; i < CIN; i += 256) s2s[i] = g_s2[b * CIN + i];
    __syncthreads();
    int warp = threadIdx.x >> 5, lane = threadIdx.x & 31;
    for (int j = 0; j < 8; j++) {
        int cout = cout0 + warp + 8 * j;
        const float* wq = g_wsq + cout * CIN;
        float sum = 0.f;
        for (int d = lane; d < CIN; d += 32) sum += wq[d] * s2s[d];
        #pragma unroll
        for (int o = 16; o; o >>= 1) sum += __shfl_xor_sync(0xFFFFFFFFu, sum, o);
        if (lane == 0) g_demod[b * COUT + cout] = rsqrtf(sum + 1e-8f);
    }
}

// ---------------- kernel 4: the conv + noise + bias + leaky-relu epilogue
// grid: (COUT/TC, B), 256 threads. Each thread: 4 positions (h = hbase+8p, w=lane) x 16 couts.
__global__ __launch_bounds__(256, 2) void k_conv(
    const float* __restrict__ x,
    const float* __restrict__ noise,
    const float* __restrict__ noise_weight,
    const float* __restrict__ act_bias,
    float* __restrict__ out)
{
    __shared__ __align__(16) float xs[CCHUNK][34 * 34];
    __shared__ __align__(16) float ws[CCHUNK][KK][TC];

    const int b     = blockIdx.y;
    const int cout0 = blockIdx.x * TC;
    const int tid   = threadIdx.x;
    const int wcol  = tid & 31;
    const int hbase = tid >> 5;

    float acc[4][TC];
    #pragma unroll
    for (int p = 0; p < 4; p++)
        #pragma unroll
        for (int c = 0; c < TC; c++) acc[p][c] = 0.f;

    const float* xb = x + (long)b * CIN * (H * W);
    const float* sb = g_s + b * CIN;

    for (int cin0 = 0; cin0 < CIN; cin0 += CCHUNK) {
        __syncthreads();   // previous compute done before overwriting tiles

        // ---- load weight tile [CCHUNK][9][TC], coalesced from g_wt
        for (int i = tid; i < CCHUNK * KK * TC; i += 256) {
            int c    = i & (TC - 1);
            int rest = i / TC;
            int kk   = rest % KK;
            int ci   = rest / KK;
            ws[ci][kk][c] = g_wt[((cin0 + ci) * KK + kk) * COUT + cout0 + c];
        }

        // ---- load modulated x tile with halo, zero padded
        #pragma unroll 1
        for (int ci = 0; ci < CCHUNK; ci++) {
            float sv = sb[cin0 + ci];
            const float* xp = xb + (cin0 + ci) * (H * W);
            for (int r = tid; r < 34 * 34; r += 256) {
                int hh = r / 34;
                int ww = r - hh * 34;
                int gh = hh - 1, gw = ww - 1;
                float v = 0.f;
                if ((unsigned)gh < (unsigned)H && (unsigned)gw < (unsigned)W)
                    v = xp[gh * W + gw] * sv;
                xs[ci][r] = v;
            }
        }
        __syncthreads();

        // ---- compute: 8 LDS per 64 FFMA
        #pragma unroll 2
        for (int ci = 0; ci < CCHUNK; ci++) {
            #pragma unroll
            for (int ky = 0; ky < 3; ky++) {
                #pragma unroll
                for (int kx = 0; kx < 3; kx++) {
                    const float* wrow = &ws[ci][ky * 3 + kx][0];
                    float4 w0 = *(const float4*)(wrow + 0);
                    float4 w1 = *(const float4*)(wrow + 4);
                    float4 w2 = *(const float4*)(wrow + 8);
                    float4 w3 = *(const float4*)(wrow + 12);
                    float xv[4];
                    #pragma unroll
                    for (int p = 0; p < 4; p++)
                        xv[p] = xs[ci][(hbase + 8 * p + ky) * 34 + (wcol + kx)];
                    #pragma unroll
                    for (int p = 0; p < 4; p++) {
                        acc[p][0]  += w0.x * xv[p];
                        acc[p][1]  += w0.y * xv[p];
                        acc[p][2]  += w0.z * xv[p];
                        acc[p][3]  += w0.w * xv[p];
                        acc[p][4]  += w1.x * xv[p];
                        acc[p][5]  += w1.y * xv[p];
                        acc[p][6]  += w1.z * xv[p];
                        acc[p][7]  += w1.w * xv[p];
                        acc[p][8]  += w2.x * xv[p];
                        acc[p][9]  += w2.y * xv[p];
                        acc[p][10] += w2.z * xv[p];
                        acc[p][11] += w2.w * xv[p];
                        acc[p][12] += w3.x * xv[p];
                        acc[p][13] += w3.y * xv[p];
                        acc[p][14] += w3.z * xv[p];
                        acc[p][15] += w3.w * xv[p];
                    }
                }
            }
        }
    }

    // ---- epilogue: demod scale, noise, bias, leaky-relu * sqrt2
    const float nwv = noise_weight[0];
    float nz[4];
    #pragma unroll
    for (int p = 0; p < 4; p++) {
        int h = hbase + 8 * p;
        nz[p] = noise[b * (H * W) + h * W + wcol] * nwv;
    }
    #pragma unroll
    for (int c = 0; c < TC; c++) {
        float dm   = g_demod[b * COUT + cout0 + c];
        float bias = act_bias[cout0 + c];
        #pragma unroll
        for (int p = 0; p < 4; p++) {
            int h = hbase + 8 * p;
            float v = acc[p][c] * dm + nz[p] + bias;
            v = (v > 0.f) ? v : 0.2f * v;
            out[(((long)b * COUT + cout0 + c) * H + h) * W + wcol] = v * SQRT2;
        }
    }
}

// ---------------- launch ----------------
extern "C" void kernel_launch(void* const* d_in, const int* in_sizes, int n_in,
                              void* d_out, int out_size) {
    const float* x       = (const float*)d_in[0];
    const float* style   = (const float*)d_in[1];
    const float* noise   = (const float*)d_in[2];
    const float* weight  = (const float*)d_in[3];
    const float* mod_w   = (const float*)d_in[4];
    const float* mod_b   = (const float*)d_in[5];
    const float* nw      = (const float*)d_in[6];
    const float* act_b   = (const float*)d_in[7];
    float* out = (float*)d_out;

    k_style<<<B, 256>>>(style, mod_w, mod_b);
    k_prep_weight<<<CIN, COUT>>>(weight);
    k_demod<<<dim3(COUT / 64, B), 256>>>();
    k_conv<<<dim3(COUT / TC, B), 256>>>(x, noise, nw, act_b, out);
}

// round 4
// speedup vs baseline: 3.1639x; 3.1639x over previous
#include <cuda_runtime.h>
#include <cuda_bf16.h>
#include <math.h>
#include <stdint.h>

#define B     16
#define CIN   512
#define COUT  512
#define SD    512
#define H     32
#define W     32

#define CONV_SCALE 0.014731391274719736f   // 1/sqrt(512*9)
#define MOD_SCALE  0.044194173824159216f   // 1/sqrt(512)
#define SQRT2      1.4142135623730951f

#define KP        1536                      // K' per kk = 3*512 (triplet split)
#define ITERS     216                       // 9 * (1536/64)
#define TM        128
#define TN        256
#define THREADS   512
#define STAGES    3
#define STAGE_BYTES 49152                   // A 16KB + B 32KB
#define SMEM_DYN  (STAGES * STAGE_BYTES + 1024)

// ---------------- scratch ----------------
__device__ float g_s    [B * CIN];
__device__ float g_s2   [B * CIN];
__device__ float g_demod[B * COUT];
__device__ float g_wsq  [COUT * CIN];
__device__ __nv_bfloat16 g_p3[(size_t)B * 34 * 34 * KP];   // [b][h'][w'][k']
__device__ __nv_bfloat16 g_w3[(size_t)9 * COUT * KP];      // [kk][cout][k']

// ---------------- PTX helpers (all sm_80-level) ----------------
__device__ __forceinline__ uint32_t smem_u32(const void* p) {
    uint32_t a;
    asm("{ .reg .u64 t; cvta.to.shared.u64 t, %1; cvt.u32.u64 %0, t; }" : "=r"(a) : "l"(p));
    return a;
}
__device__ __forceinline__ void cp_async16(uint32_t dst, const void* src) {
    asm volatile("cp.async.cg.shared.global [%0], [%1], 16;" :: "r"(dst), "l"(src));
}
__device__ __forceinline__ void cp_commit() {
    asm volatile("cp.async.commit_group;" ::: "memory");
}
__device__ __forceinline__ void cp_wait2() {
    asm volatile("cp.async.wait_group 2;" ::: "memory");
}
__device__ __forceinline__ void ldsm4(uint32_t* r, uint32_t addr) {
    asm volatile("ldmatrix.sync.aligned.m8n8.x4.shared.b16 {%0,%1,%2,%3}, [%4];"
                 : "=r"(r[0]), "=r"(r[1]), "=r"(r[2]), "=r"(r[3]) : "r"(addr));
}
__device__ __forceinline__ void mma_bf16(float* d, const uint32_t* a, const uint32_t* b) {
    asm volatile("mma.sync.aligned.m16n8k16.row.col.f32.bf16.bf16.f32 "
                 "{%0,%1,%2,%3}, {%4,%5,%6,%7}, {%8,%9}, {%0,%1,%2,%3};"
                 : "+f"(d[0]), "+f"(d[1]), "+f"(d[2]), "+f"(d[3])
                 : "r"(a[0]), "r"(a[1]), "r"(a[2]), "r"(a[3]), "r"(b[0]), "r"(b[1]));
}

// ---------------- kernel 1: style modulation ----------------
__global__ void k_style(const float* __restrict__ style,
                        const float* __restrict__ mod_w,
                        const float* __restrict__ mod_b) {
    int b = blockIdx.x;
    __shared__ float st[SD];
    for (int i = threadIdx.x; i < SD; i += 256) st[i] = style[b * SD + i];
    __syncthreads();
    int warp = threadIdx.x >> 5, lane = threadIdx.x & 31;
    for (int cin = warp; cin < CIN; cin += 8) {
        const float* mw = mod_w + cin * SD;
        float sum = 0.f;
        for (int d = lane; d < SD; d += 32) sum += mw[d] * st[d];
        #pragma unroll
        for (int o = 16; o; o >>= 1) sum += __shfl_xor_sync(0xFFFFFFFFu, sum, o);
        if (lane == 0) {
            float s = sum * MOD_SCALE + mod_b[cin];
            g_s [b * CIN + cin] = s;
            g_s2[b * CIN + cin] = s * s;
        }
    }
}

// ---------------- kernel 2: wsq ----------------
__global__ void k_wsq(const float* __restrict__ weight) {
    int cin  = blockIdx.x;
    int cout = threadIdx.x;
    const float* wp = weight + (cout * CIN + cin) * 9;
    float ss = 0.f;
    #pragma unroll
    for (int kk = 0; kk < 9; kk++) { float w = wp[kk]; ss += w * w; }
    g_wsq[cout * CIN + cin] = ss * (CONV_SCALE * CONV_SCALE);
}

// ---------------- kernel 3: demod ----------------
__global__ void k_demod() {
    int b = blockIdx.y;
    int cout0 = blockIdx.x * 64;
    __shared__ float s2s[CIN];
    for (int i = threadIdx.x; i < CIN; i += 256) s2s[i] = g_s2[b * CIN + i];
    __syncthreads();
    int warp = threadIdx.x >> 5, lane = threadIdx.x & 31;
    for (int j = 0; j < 8; j++) {
        int cout = cout0 + warp + 8 * j;
        const float* wq = g_wsq + cout * CIN;
        float sum = 0.f;
        for (int d = lane; d < CIN; d += 32) sum += wq[d] * s2s[d];
        #pragma unroll
        for (int o = 16; o; o >>= 1) sum += __shfl_xor_sync(0xFFFFFFFFu, sum, o);
        if (lane == 0) g_demod[b * COUT + cout] = rsqrtf(sum + 1e-8f);
    }
}

// ---------------- kernel 4: build P3 (Ah,Ah,Al triplets, padded) ----------------
__global__ void k_prep_x(const float* __restrict__ x) {
    int bid = blockIdx.x;
    int b  = bid / 34;
    int hp = bid % 34;
    int tid = threadIdx.x;
    size_t rowbase = ((size_t)(b * 34 + hp) * 34) * KP;

    if (hp == 0 || hp == 33) {
        uint4* dst = (uint4*)(g_p3 + rowbase);
        uint4 z = {0, 0, 0, 0};
        for (int i = tid; i < 34 * KP * 2 / 16; i += 256) dst[i] = z;
        return;
    }
    int h = hp - 1;
    __shared__ float xs[256][33];

    for (int pass = 0; pass < 2; pass++) {
        int cp = pass * 256;
        __syncthreads();
        for (int i = tid; i < 256 * 32; i += 256) {
            int ci = i >> 5, w = i & 31;
            float s = g_s[b * CIN + cp + ci];
            xs[ci][w] = x[(((size_t)b * CIN + cp + ci) * H + h) * W + w] * s;
        }
        __syncthreads();
        for (int wp = 0; wp < 34; wp++) {
            int w = wp - 1;
            __nv_bfloat16* dst = g_p3 + rowbase + (size_t)wp * KP + pass * 768;
            if (w < 0 || w >= 32) {
                for (int j = tid; j < 768; j += 256) dst[j] = __float2bfloat16(0.f);
            } else {
                for (int j = tid; j < 768; j += 256) {
                    int c = j / 3, jj = j - c * 3;
                    float v = xs[c][w];
                    __nv_bfloat16 hi = __float2bfloat16(v);
                    __nv_bfloat16 o = (jj < 2) ? hi : __float2bfloat16(v - __bfloat162float(hi));
                    dst[j] = o;
                }
            }
        }
    }
}

// ---------------- kernel 5: build W3 (Wh,Wl,Wh triplets) ----------------
__global__ void k_prep_w(const float* __restrict__ weight) {
    int cout = blockIdx.x;
    int tid = threadIdx.x;
    for (int kk = 0; kk < 9; kk++) {
        __nv_bfloat16* dst = g_w3 + ((size_t)kk * COUT + cout) * KP;
        for (int j = tid; j < KP; j += 256) {
            int c = j / 3, jj = j - c * 3;
            float w = weight[((size_t)cout * CIN + c) * 9 + kk] * CONV_SCALE;
            __nv_bfloat16 hi = __float2bfloat16(w);
            __nv_bfloat16 o = (jj == 1) ? __float2bfloat16(w - __bfloat162float(hi)) : hi;
            dst[j] = o;
        }
    }
}

// ---------------- kernel 6: mma.sync GEMM + fused epilogue ----------------
// grid 256: nt = bx&1 (cout half), mt = bx>>1 (128 spatial rows = 4 h-rows of one b)
__global__ __launch_bounds__(THREADS, 1) void k_gemm(
    const float* __restrict__ noise,
    const float* __restrict__ noise_weight,
    const float* __restrict__ act_bias,
    float* __restrict__ out)
{
    extern __shared__ char dyn_smem[];
    const uint32_t base = (smem_u32(dyn_smem) + 1023u) & ~1023u;

    const int tid  = threadIdx.x;
    const int lane = tid & 31;
    const int wid  = tid >> 5;
    const int nt = blockIdx.x & 1;
    const int mt = blockIdx.x >> 1;
    const int b  = mt >> 3;
    const int h0 = (mt & 7) * 4;
    const int cout0 = nt * TN;

    // ---- loader state (each thread: 2 A chunks, 4 B chunks of 16B) ----
    const int rA  = tid >> 2;                 // A row 0..127
    const int ccA = 2 * (tid & 3);            // A chunks ccA, ccA+1
    const int dhA = rA >> 5, wA = rA & 31;
    const int rB  = tid >> 1;                 // B row 0..255
    const int ccB = 4 * (tid & 1);            // B chunks ccB..ccB+3
    uint32_t dstA[2], dstB[4];
    #pragma unroll
    for (int j = 0; j < 2; j++)
        dstA[j] = rA * 128 + (((ccA + j) ^ (rA & 7)) << 4);
    #pragma unroll
    for (int j = 0; j < 4; j++)
        dstB[j] = 16384 + rB * 128 + (((ccB + j) ^ (rB & 7)) << 4);

    // ---- compute-phase per-thread constants ----
    const int sub = lane >> 3, l7 = lane & 7;
    const int warp_m = wid & 1, warp_n = wid >> 1;
    const uint32_t aRowBase = (uint32_t)(warp_m * 64 + (sub & 1) * 8 + l7) * 128;
    const int aHalf = sub >> 1;
    uint32_t bRowBase[2];
    const int bHalf = sub & 1;
    #pragma unroll
    for (int p = 0; p < 2; p++)
        bRowBase[p] = 16384 + (uint32_t)(warp_n * 32 + p * 16 + (sub >> 1) * 8 + l7) * 128;

    float acc[4][4][4];
    #pragma unroll
    for (int mi = 0; mi < 4; mi++)
        #pragma unroll
        for (int nj = 0; nj < 4; nj++)
            #pragma unroll
            for (int q = 0; q < 4; q++) acc[mi][nj][q] = 0.f;

    // ---- stage loader ----
    auto load_stage = [&](int st, int kk, int ky, int kx, int k0) {
        uint32_t sb = base + st * STAGE_BYTES;
        const __nv_bfloat16* srcA = g_p3
            + ((size_t)((b * 34 + h0 + dhA + ky) * 34) + (wA + kx)) * KP + k0 + ccA * 8;
        cp_async16(sb + dstA[0], srcA);
        cp_async16(sb + dstA[1], srcA + 8);
        const __nv_bfloat16* srcB = g_w3
            + ((size_t)(kk * COUT + cout0 + rB)) * KP + k0 + ccB * 8;
        #pragma unroll
        for (int j = 0; j < 4; j++) cp_async16(sb + dstB[j], srcB + j * 8);
    };

    // prologue: stages for it=0 (kk=0,ch=0) and it=1 (kk=0,ch=1)
    load_stage(0, 0, 0, 0, 0);  cp_commit();
    load_stage(1, 0, 0, 0, 64); cp_commit();

    // incremental indices for the NEXT stage to load (it=2)
    int lkk = 0, lky = 0, lkx = 0, lch = 2;

    int st = 0;
    for (int it = 0; it < ITERS; ++it) {
        if (it) __syncthreads();            // prior compute done before overwrite
        if (it + 2 < ITERS) {
            load_stage((st + 2) % STAGES, lkk, lky, lkx, lch * 64);
            if (++lch == 24) { lch = 0; ++lkk; if (++lkx == 3) { lkx = 0; ++lky; } }
        }
        cp_commit();
        cp_wait2();
        __syncthreads();

        uint32_t sb = base + st * STAGE_BYTES;
        #pragma unroll
        for (int ks = 0; ks < 4; ks++) {
            uint32_t br[2][4];
            ldsm4(br[0], sb + bRowBase[0] + (((ks * 2 + bHalf) ^ l7) << 4));
            ldsm4(br[1], sb + bRowBase[1] + (((ks * 2 + bHalf) ^ l7) << 4));
            #pragma unroll
            for (int mi = 0; mi < 4; mi++) {
                uint32_t ar[4];
                ldsm4(ar, sb + aRowBase + mi * 2048 + (((ks * 2 + aHalf) ^ l7) << 4));
                mma_bf16(acc[mi][0], ar, &br[0][0]);
                mma_bf16(acc[mi][1], ar, &br[0][2]);
                mma_bf16(acc[mi][2], ar, &br[1][0]);
                mma_bf16(acc[mi][3], ar, &br[1][2]);
            }
        }
        if (++st == STAGES) st = 0;
    }

    // ---- epilogue ----
    const int grp = lane >> 2, qt = lane & 3;
    const float nwv = noise_weight[0];
    #pragma unroll
    for (int mi = 0; mi < 4; mi++) {
        #pragma unroll
        for (int rr = 0; rr < 2; rr++) {
            int ml = warp_m * 64 + mi * 16 + grp + rr * 8;
            int h  = h0 + (ml >> 5);
            int w  = ml & 31;
            float nz = noise[(b * H + h) * W + w] * nwv;
            #pragma unroll
            for (int nj = 0; nj < 4; nj++) {
                int cout = cout0 + warp_n * 32 + nj * 8 + qt * 2;
                #pragma unroll
                for (int cc = 0; cc < 2; cc++) {
                    float v = acc[mi][nj][rr * 2 + cc] * g_demod[b * COUT + cout + cc]
                              + nz + act_bias[cout + cc];
                    v = (v > 0.f) ? v : 0.2f * v;
                    out[(((size_t)b * COUT + cout + cc) * H + h) * W + w] = v * SQRT2;
                }
            }
        }
    }
}

// ---------------- launch ----------------
extern "C" void kernel_launch(void* const* d_in, const int* in_sizes, int n_in,
                              void* d_out, int out_size) {
    const float* x       = (const float*)d_in[0];
    const float* style   = (const float*)d_in[1];
    const float* noise   = (const float*)d_in[2];
    const float* weight  = (const float*)d_in[3];
    const float* mod_w   = (const float*)d_in[4];
    const float* mod_b   = (const float*)d_in[5];
    const float* nw      = (const float*)d_in[6];
    const float* act_b   = (const float*)d_in[7];
    float* out = (float*)d_out;

    cudaFuncSetAttribute(k_gemm, cudaFuncAttributeMaxDynamicSharedMemorySize, SMEM_DYN);

    k_style<<<B, 256>>>(style, mod_w, mod_b);
    k_wsq<<<CIN, COUT>>>(weight);
    k_demod<<<dim3(COUT / 64, B), 256>>>();
    k_prep_x<<<B * 34, 256>>>(x);
    k_prep_w<<<COUT, 256>>>(weight);
    k_gemm<<<256, THREADS, SMEM_DYN>>>(noise, nw, act_b, out);
}

// round 5
// speedup vs baseline: 7.3409x; 2.3202x over previous
#include <cuda_runtime.h>
#include <cuda_fp16.h>
#include <math.h>
#include <stdint.h>

#define B     16
#define CIN   512
#define COUT  512
#define SD    512
#define H     32
#define W     32

#define CONV_SCALE 0.014731391274719736f   // 1/sqrt(512*9)
#define MOD_SCALE  0.044194173824159216f   // 1/sqrt(512)
#define SQRT2      1.4142135623730951f

#define KP        512                       // K per kk (fp16, no split)
#define ITERS     72                        // 9 * (512/64)
#define TM        128
#define TN        256
#define THREADS   512
#define STAGES    3
#define STAGE_BYTES 49152                   // A 16KB + B 32KB
#define SMEM_DYN  (STAGES * STAGE_BYTES + 1024)

// ---------------- scratch ----------------
__device__ float g_s    [B * CIN];
__device__ float g_s2   [B * CIN];
__device__ float g_demod[B * COUT];
__device__ float g_wsq  [COUT * CIN];
__device__ __half g_p3[(size_t)B * 34 * 34 * KP];   // [b][h'][w'][cin] 18.9MB
__device__ __half g_w3[(size_t)9 * COUT * KP];      // [kk][cout][cin]   4.7MB

// ---------------- PTX helpers (all sm_80-level) ----------------
__device__ __forceinline__ uint32_t smem_u32(const void* p) {
    uint32_t a;
    asm("{ .reg .u64 t; cvta.to.shared.u64 t, %1; cvt.u32.u64 %0, t; }" : "=r"(a) : "l"(p));
    return a;
}
__device__ __forceinline__ void cp_async16(uint32_t dst, const void* src) {
    asm volatile("cp.async.cg.shared.global [%0], [%1], 16;" :: "r"(dst), "l"(src));
}
__device__ __forceinline__ void cp_commit() {
    asm volatile("cp.async.commit_group;" ::: "memory");
}
__device__ __forceinline__ void cp_wait2() {
    asm volatile("cp.async.wait_group 2;" ::: "memory");
}
__device__ __forceinline__ void ldsm4(uint32_t* r, uint32_t addr) {
    asm volatile("ldmatrix.sync.aligned.m8n8.x4.shared.b16 {%0,%1,%2,%3}, [%4];"
                 : "=r"(r[0]), "=r"(r[1]), "=r"(r[2]), "=r"(r[3]) : "r"(addr));
}
__device__ __forceinline__ void mma_f16(float* d, const uint32_t* a, const uint32_t* b) {
    asm volatile("mma.sync.aligned.m16n8k16.row.col.f32.f16.f16.f32 "
                 "{%0,%1,%2,%3}, {%4,%5,%6,%7}, {%8,%9}, {%0,%1,%2,%3};"
                 : "+f"(d[0]), "+f"(d[1]), "+f"(d[2]), "+f"(d[3])
                 : "r"(a[0]), "r"(a[1]), "r"(a[2]), "r"(a[3]), "r"(b[0]), "r"(b[1]));
}

// ---------------- kernel 1: style modulation ----------------
__global__ void k_style(const float* __restrict__ style,
                        const float* __restrict__ mod_w,
                        const float* __restrict__ mod_b) {
    int b = blockIdx.x;
    __shared__ float st[SD];
    for (int i = threadIdx.x; i < SD; i += 256) st[i] = style[b * SD + i];
    __syncthreads();
    int warp = threadIdx.x >> 5, lane = threadIdx.x & 31;
    for (int cin = warp; cin < CIN; cin += 8) {
        const float* mw = mod_w + cin * SD;
        float sum = 0.f;
        for (int d = lane; d < SD; d += 32) sum += mw[d] * st[d];
        #pragma unroll
        for (int o = 16; o; o >>= 1) sum += __shfl_xor_sync(0xFFFFFFFFu, sum, o);
        if (lane == 0) {
            float s = sum * MOD_SCALE + mod_b[cin];
            g_s [b * CIN + cin] = s;
            g_s2[b * CIN + cin] = s * s;
        }
    }
}

// ---------------- kernel 2: wsq ----------------
__global__ void k_wsq(const float* __restrict__ weight) {
    int cin  = blockIdx.x;
    int cout = threadIdx.x;
    const float* wp = weight + (cout * CIN + cin) * 9;
    float ss = 0.f;
    #pragma unroll
    for (int kk = 0; kk < 9; kk++) { float w = wp[kk]; ss += w * w; }
    g_wsq[cout * CIN + cin] = ss * (CONV_SCALE * CONV_SCALE);
}

// ---------------- kernel 3: demod ----------------
__global__ void k_demod() {
    int b = blockIdx.y;
    int cout0 = blockIdx.x * 64;
    __shared__ float s2s[CIN];
    for (int i = threadIdx.x; i < CIN; i += 256) s2s[i] = g_s2[b * CIN + i];
    __syncthreads();
    int warp = threadIdx.x >> 5, lane = threadIdx.x & 31;
    for (int j = 0; j < 8; j++) {
        int cout = cout0 + warp + 8 * j;
        const float* wq = g_wsq + cout * CIN;
        float sum = 0.f;
        for (int d = lane; d < CIN; d += 32) sum += wq[d] * s2s[d];
        #pragma unroll
        for (int o = 16; o; o >>= 1) sum += __shfl_xor_sync(0xFFFFFFFFu, sum, o);
        if (lane == 0) g_demod[b * COUT + cout] = rsqrtf(sum + 1e-8f);
    }
}

// ---------------- kernel 4: build P3 [b][h'][w'][cin] fp16 (modulated, padded) ----------------
__global__ void k_prep_x(const float* __restrict__ x) {
    int bid = blockIdx.x;
    int b  = bid / 34;
    int hp = bid % 34;
    int tid = threadIdx.x;
    size_t rowbase = ((size_t)(b * 34 + hp) * 34) * KP;

    if (hp == 0 || hp == 33) {
        uint4* dst = (uint4*)(g_p3 + rowbase);
        uint4 z = {0, 0, 0, 0};
        for (int i = tid; i < 34 * KP * 2 / 16; i += 256) dst[i] = z;
        return;
    }
    int h = hp - 1;
    __shared__ float xs[256][33];

    for (int pass = 0; pass < 2; pass++) {
        int cp = pass * 256;
        __syncthreads();
        for (int i = tid; i < 256 * 32; i += 256) {
            int ci = i >> 5, w = i & 31;
            float s = g_s[b * CIN + cp + ci];
            xs[ci][w] = x[(((size_t)b * CIN + cp + ci) * H + h) * W + w] * s;
        }
        __syncthreads();
        for (int wp = 0; wp < 34; wp++) {
            int w = wp - 1;
            __half* dst = g_p3 + rowbase + (size_t)wp * KP + pass * 256;
            if (w < 0 || w >= 32) {
                for (int j = tid; j < 256; j += 256) dst[j] = __float2half_rn(0.f);
            } else {
                for (int j = tid; j < 256; j += 256)
                    dst[j] = __float2half_rn(xs[j][w]);
            }
        }
    }
}

// ---------------- kernel 5: build W3 [kk][cout][cin] fp16 ----------------
__global__ void k_prep_w(const float* __restrict__ weight) {
    int cout = blockIdx.x;
    int tid = threadIdx.x;
    for (int kk = 0; kk < 9; kk++) {
        __half* dst = g_w3 + ((size_t)kk * COUT + cout) * KP;
        for (int j = tid; j < KP; j += 256)
            dst[j] = __float2half_rn(weight[((size_t)cout * CIN + j) * 9 + kk] * CONV_SCALE);
    }
}

// ---------------- kernel 6: mma.sync GEMM + fused epilogue ----------------
// grid 256: nt = bx&1 (cout half), mt = bx>>1 (128 spatial rows = 4 h-rows of one b)
__global__ __launch_bounds__(THREADS, 1) void k_gemm(
    const float* __restrict__ noise,
    const float* __restrict__ noise_weight,
    const float* __restrict__ act_bias,
    float* __restrict__ out)
{
    extern __shared__ char dyn_smem[];
    const uint32_t base = (smem_u32(dyn_smem) + 1023u) & ~1023u;

    const int tid  = threadIdx.x;
    const int lane = tid & 31;
    const int wid  = tid >> 5;
    const int nt = blockIdx.x & 1;
    const int mt = blockIdx.x >> 1;
    const int b  = mt >> 3;
    const int h0 = (mt & 7) * 4;
    const int cout0 = nt * TN;

    // ---- loader state (each thread: 2 A chunks, 4 B chunks of 16B) ----
    const int rA  = tid >> 2;                 // A row 0..127
    const int ccA = 2 * (tid & 3);            // A chunks ccA, ccA+1
    const int dhA = rA >> 5, wA = rA & 31;
    const int rB  = tid >> 1;                 // B row 0..255
    const int ccB = 4 * (tid & 1);            // B chunks ccB..ccB+3
    uint32_t dstA[2], dstB[4];
    #pragma unroll
    for (int j = 0; j < 2; j++)
        dstA[j] = rA * 128 + (((ccA + j) ^ (rA & 7)) << 4);
    #pragma unroll
    for (int j = 0; j < 4; j++)
        dstB[j] = 16384 + rB * 128 + (((ccB + j) ^ (rB & 7)) << 4);

    // ---- compute-phase per-thread constants ----
    const int sub = lane >> 3, l7 = lane & 7;
    const int warp_m = wid & 1, warp_n = wid >> 1;
    const uint32_t aRowBase = (uint32_t)(warp_m * 64 + (sub & 1) * 8 + l7) * 128;
    const int aHalf = sub >> 1;
    uint32_t bRowBase[2];
    const int bHalf = sub & 1;
    #pragma unroll
    for (int p = 0; p < 2; p++)
        bRowBase[p] = 16384 + (uint32_t)(warp_n * 32 + p * 16 + (sub >> 1) * 8 + l7) * 128;

    float acc[4][4][4];
    #pragma unroll
    for (int mi = 0; mi < 4; mi++)
        #pragma unroll
        for (int nj = 0; nj < 4; nj++)
            #pragma unroll
            for (int q = 0; q < 4; q++) acc[mi][nj][q] = 0.f;

    // ---- stage loader ----
    auto load_stage = [&](int st, int kk, int ky, int kx, int k0) {
        uint32_t sb = base + st * STAGE_BYTES;
        const __half* srcA = g_p3
            + ((size_t)((b * 34 + h0 + dhA + ky) * 34) + (wA + kx)) * KP + k0 + ccA * 8;
        cp_async16(sb + dstA[0], srcA);
        cp_async16(sb + dstA[1], srcA + 8);
        const __half* srcB = g_w3
            + ((size_t)(kk * COUT + cout0 + rB)) * KP + k0 + ccB * 8;
        #pragma unroll
        for (int j = 0; j < 4; j++) cp_async16(sb + dstB[j], srcB + j * 8);
    };

    // prologue: stages for it=0 (kk=0,ch=0) and it=1 (kk=0,ch=1)
    load_stage(0, 0, 0, 0, 0);  cp_commit();
    load_stage(1, 0, 0, 0, 64); cp_commit();

    // incremental indices for the NEXT stage to load (it=2)
    int lkk = 0, lky = 0, lkx = 0, lch = 2;

    int st = 0;
    for (int it = 0; it < ITERS; ++it) {
        if (it) __syncthreads();            // prior compute done before overwrite
        if (it + 2 < ITERS) {
            load_stage((st + 2) % STAGES, lkk, lky, lkx, lch * 64);
            if (++lch == 8) { lch = 0; ++lkk; if (++lkx == 3) { lkx = 0; ++lky; } }
        }
        cp_commit();
        cp_wait2();
        __syncthreads();

        uint32_t sb = base + st * STAGE_BYTES;
        #pragma unroll
        for (int ks = 0; ks < 4; ks++) {
            uint32_t br[2][4];
            ldsm4(br[0], sb + bRowBase[0] + (((ks * 2 + bHalf) ^ l7) << 4));
            ldsm4(br[1], sb + bRowBase[1] + (((ks * 2 + bHalf) ^ l7) << 4));
            #pragma unroll
            for (int mi = 0; mi < 4; mi++) {
                uint32_t ar[4];
                ldsm4(ar, sb + aRowBase + mi * 2048 + (((ks * 2 + aHalf) ^ l7) << 4));
                mma_f16(acc[mi][0], ar, &br[0][0]);
                mma_f16(acc[mi][1], ar, &br[0][2]);
                mma_f16(acc[mi][2], ar, &br[1][0]);
                mma_f16(acc[mi][3], ar, &br[1][2]);
            }
        }
        if (++st == STAGES) st = 0;
    }

    // ---- epilogue ----
    const int grp = lane >> 2, qt = lane & 3;
    const float nwv = noise_weight[0];
    #pragma unroll
    for (int mi = 0; mi < 4; mi++) {
        #pragma unroll
        for (int rr = 0; rr < 2; rr++) {
            int ml = warp_m * 64 + mi * 16 + grp + rr * 8;
            int h  = h0 + (ml >> 5);
            int w  = ml & 31;
            float nz = noise[(b * H + h) * W + w] * nwv;
            #pragma unroll
            for (int nj = 0; nj < 4; nj++) {
                int cout = cout0 + warp_n * 32 + nj * 8 + qt * 2;
                #pragma unroll
                for (int cc = 0; cc < 2; cc++) {
                    float v = acc[mi][nj][rr * 2 + cc] * g_demod[b * COUT + cout + cc]
                              + nz + act_bias[cout + cc];
                    v = (v > 0.f) ? v : 0.2f * v;
                    out[(((size_t)b * COUT + cout + cc) * H + h) * W + w] = v * SQRT2;
                }
            }
        }
    }
}

// ---------------- launch ----------------
extern "C" void kernel_launch(void* const* d_in, const int* in_sizes, int n_in,
                              void* d_out, int out_size) {
    const float* x       = (const float*)d_in[0];
    const float* style   = (const float*)d_in[1];
    const float* noise   = (const float*)d_in[2];
    const float* weight  = (const float*)d_in[3];
    const float* mod_w   = (const float*)d_in[4];
    const float* mod_b   = (const float*)d_in[5];
    const float* nw      = (const float*)d_in[6];
    const float* act_b   = (const float*)d_in[7];
    float* out = (float*)d_out;

    cudaFuncSetAttribute(k_gemm, cudaFuncAttributeMaxDynamicSharedMemorySize, SMEM_DYN);

    k_style<<<B, 256>>>(style, mod_w, mod_b);
    k_wsq<<<CIN, COUT>>>(weight);
    k_demod<<<dim3(COUT / 64, B), 256>>>();
    k_prep_x<<<B * 34, 256>>>(x);
    k_prep_w<<<COUT, 256>>>(weight);
    k_gemm<<<256, THREADS, SMEM_DYN>>>(noise, nw, act_b, out);
}